// round 12
// baseline (speedup 1.0000x reference)
#include <cuda_runtime.h>
#include <cuda_bf16.h>
#include <math.h>
#include <cstdint>

// Problem constants
#define B_    4
#define N_    4096
#define E_    1024
#define H_    16
#define MTOT  16384        // B*N
#define EPSN  1e-4f
#define SCALE 2.0f         // H^0.25
#define FSCALE 0.125f      // PD^-0.5
#define QMAX  16000.0f     // per-row quantization target (fits 128*125+64)

// ---------------------------------------------------------------------------
// Scratch (device globals: allocation-free rule)
// ---------------------------------------------------------------------------
__device__ float g_q [16777216];     // (B,N,E) q proj fp32
__device__ float g_k [16777216];     // (B,N,E) k proj fp32; later ao fp32
__device__ float g_v [16777216];     // (B,N,E) v proj fp32
__device__ float g_kvp[8388608];     // per block partial kv (128x64)
__device__ float g_kv [524288];      // per bh kv (128x64)
__device__ int8_t g_xq1[16777216];   // X (or ao) int8 hi slice
__device__ int8_t g_xq2[16777216];   // X (or ao) int8 lo slice
__device__ int8_t g_wq1[4194304];    // 4 x 1024x1024 W hi slices
__device__ int8_t g_wq2[4194304];    // 4 x 1024x1024 W lo slices
__device__ float g_sx[16384];        // per-row scale of X (or ao)
__device__ float g_sw[4096];         // per-row scale of W (4 matrices)

__device__ __forceinline__ float* sel_buf(int s) {
    return s == 0 ? g_q : (s == 1 ? g_k : g_v);
}

// ---------------------------------------------------------------------------
// PTX helpers (base-target sm_103 safe)
// ---------------------------------------------------------------------------
__device__ __forceinline__ uint32_t smem_u32(const void* p) {
    uint32_t a;
    asm("{ .reg .u64 t; cvta.to.shared.u64 t, %1; cvt.u32.u64 %0, t; }"
        : "=r"(a) : "l"(p));
    return a;
}
__device__ __forceinline__ void cpasync16(uint32_t dst, const void* src) {
    asm volatile("cp.async.cg.shared.global [%0], [%1], 16;" :: "r"(dst), "l"(src));
}
#define CP_COMMIT()  asm volatile("cp.async.commit_group;" ::: "memory")
#define CP_WAIT(n)   asm volatile("cp.async.wait_group %0;" :: "n"(n) : "memory")

__device__ __forceinline__ void ldsm4(uint32_t* r, uint32_t addr) {
    asm volatile("ldmatrix.sync.aligned.m8n8.x4.shared.b16 {%0,%1,%2,%3}, [%4];"
                 : "=r"(r[0]), "=r"(r[1]), "=r"(r[2]), "=r"(r[3]) : "r"(addr));
}
// int8 MMA: m16n8k32, s32 accumulate
__device__ __forceinline__ void mma_s8(uint32_t* d, const uint32_t* a, const uint32_t* b) {
    asm volatile(
        "mma.sync.aligned.m16n8k32.row.col.s32.s8.s8.s32 "
        "{%0,%1,%2,%3}, {%4,%5,%6,%7}, {%8,%9}, {%0,%1,%2,%3};"
        : "+r"(d[0]), "+r"(d[1]), "+r"(d[2]), "+r"(d[3])
        : "r"(a[0]), "r"(a[1]), "r"(a[2]), "r"(a[3]), "r"(b[0]), "r"(b[1]));
}

// ---------------------------------------------------------------------------
// Row quantization: fp32 row (1024) -> 2 int8 slices (radix 128) + scale.
// q = round(x/s), s = rowmax/QMAX; a1 = floor((q+64)/128), a2 = q - 128*a1.
// ssel: 0 = external src, 1 = g_k (ao).  dsel: 0 = X/ao, 1..4 = W0..W3.
// grid.x = rows (1024 cols each), 256 threads.
// ---------------------------------------------------------------------------
__global__ __launch_bounds__(256) void quant_rows(const float* __restrict__ xext,
                                                  int ssel, int dsel)
{
    const float* src = (ssel == 0) ? xext : g_k;
    int8_t *q1, *q2; float* sA; size_t rbase;
    if (dsel == 0) { q1 = g_xq1; q2 = g_xq2; sA = g_sx; rbase = 0; }
    else {
        q1 = g_wq1 + (size_t)(dsel - 1) * 1048576;
        q2 = g_wq2 + (size_t)(dsel - 1) * 1048576;
        sA = g_sw + (dsel - 1) * 1024; rbase = 0;
    }
    const int row = blockIdx.x, tid = threadIdx.x;
    const int lane = tid & 31, warp = tid >> 5;
    __shared__ float red[8];
    __shared__ float s_inv[2];

    float4 v = ((const float4*)(src + (size_t)row * 1024))[tid];
    float m4 = fmaxf(fmaxf(fabsf(v.x), fabsf(v.y)), fmaxf(fabsf(v.z), fabsf(v.w)));
#pragma unroll
    for (int off = 16; off; off >>= 1)
        m4 = fmaxf(m4, __shfl_xor_sync(0xffffffffu, m4, off));
    if (lane == 0) red[warp] = m4;
    __syncthreads();
    if (tid == 0) {
        float bm = red[0];
#pragma unroll
        for (int i = 1; i < 8; i++) bm = fmaxf(bm, red[i]);
        float s = (bm > 0.f) ? bm / QMAX : 1.0f;
        s_inv[0] = s;
        s_inv[1] = (bm > 0.f) ? QMAX / bm : 0.0f;
        sA[row] = s;
    }
    __syncthreads();
    const float inv = s_inv[1];

    int qa[4];
    qa[0] = __float2int_rn(v.x * inv);
    qa[1] = __float2int_rn(v.y * inv);
    qa[2] = __float2int_rn(v.z * inv);
    qa[3] = __float2int_rn(v.w * inv);
    char c1[4], c2[4];
#pragma unroll
    for (int i = 0; i < 4; i++) {
        int a1 = (qa[i] + 64) >> 7;           // floor((q+64)/128)
        int a2 = qa[i] - (a1 << 7);           // in [-64, 63]
        c1[i] = (char)a1; c2[i] = (char)a2;
    }
    *(char4*)(q1 + (size_t)row * 1024 + tid * 4) = make_char4(c1[0], c1[1], c1[2], c1[3]);
    *(char4*)(q2 + (size_t)row * 1024 + tid * 4) = make_char4(c2[0], c2[1], c2[2], c2[3]);
}

// ---------------------------------------------------------------------------
// int8 split GEMM (NT): Y[16384,1024] = X @ W^T + bias.
// X,W given as 2 int8 slices + per-row fp32 scales.
// X@W^T = sX[m]*sW[n]*(16384*A1B1 + 128*(A1B2 + A2B1))   [A2B2 dropped]
// 128x128 block, K-chunk 32, 256 thr (2x4 warps, 64x32 warp tile),
// 2-stage cp.async pipeline (24KB/stage), rows padded to 48B (conflict-free).
// grid (8, 128, nz); z selects W slice / bias / dst.
// ---------------------------------------------------------------------------
#define T48      48
#define QTILE_B  6144      // 128 rows * 48 bytes
#define QSTAGE_B 24576     // A1|A2|B1|B2
__global__ __launch_bounds__(256, 1) void gemm_s8(
    int wsel_base,
    const float* __restrict__ bias0, const float* __restrict__ bias1,
    const float* __restrict__ bias2,
    float* __restrict__ Yext, int ysel_base)
{
    const int z = blockIdx.z;
    const int wsel = wsel_base + z;
    const float* bias = z == 0 ? bias0 : (z == 1 ? bias1 : bias2);
    const int8_t* W1 = g_wq1 + (size_t)wsel * 1048576;
    const int8_t* W2 = g_wq2 + (size_t)wsel * 1048576;
    const float*  sW = g_sw + wsel * 1024;
    float* Y = (ysel_base < 0) ? Yext : sel_buf(ysel_base + z);

    extern __shared__ char smem[];
    const uint32_t sbase = smem_u32(smem);
    const int tid = threadIdx.x;
    const int lane = tid & 31, wid = tid >> 5;
    const int wm = wid & 1, wn = wid >> 1;      // warp tile 64 x 32
    const int m0 = blockIdx.y * 128, n0 = blockIdx.x * 128;

    uint32_t accH[4][4][4], accM[4][4][4];
#pragma unroll
    for (int a = 0; a < 4; a++)
#pragma unroll
        for (int b = 0; b < 4; b++)
#pragma unroll
            for (int c = 0; c < 4; c++) { accH[a][b][c] = 0u; accM[a][b][c] = 0u; }

    // chunk loader: 4 tiles x 128 rows x 2 segs = 1024 cp.async, 4/thread
    auto issue_chunk = [&](int c) {
        const int k0 = c * 32;
        const uint32_t dstb = sbase + (uint32_t)(c & 1) * QSTAGE_B;
#pragma unroll
        for (int it = 0; it < 4; it++) {
            const int id = it * 256 + tid;
            const int tile = id >> 8;
            const int r = (id & 255) >> 1, seg = id & 1;
            const int8_t* src;
            if (tile == 0)      src = g_xq1 + (size_t)(m0 + r) * 1024 + k0 + seg * 16;
            else if (tile == 1) src = g_xq2 + (size_t)(m0 + r) * 1024 + k0 + seg * 16;
            else if (tile == 2) src = W1 + (size_t)(n0 + r) * 1024 + k0 + seg * 16;
            else                src = W2 + (size_t)(n0 + r) * 1024 + k0 + seg * 16;
            cpasync16(dstb + tile * QTILE_B + r * T48 + seg * 16, src);
        }
        CP_COMMIT();
    };

    issue_chunk(0);
    for (int c = 0; c < 32; c++) {
        if (c + 1 < 32) { issue_chunk(c + 1); CP_WAIT(1); }
        else            { CP_WAIT(0); }
        __syncthreads();
        const uint32_t st = sbase + (uint32_t)(c & 1) * QSTAGE_B;

        // A fragments (16x32 int8 per mt): proven addressing, bytes identical
        const uint32_t arow = (uint32_t)(lane & 15);
        const uint32_t acol = (uint32_t)((lane >> 4) * 16);
        uint32_t a1f[4][4], a2f[4][4];
#pragma unroll
        for (int mt = 0; mt < 4; mt++) {
            const uint32_t off = (uint32_t)(wm * 64 + mt * 16 + arow) * T48 + acol;
            ldsm4(a1f[mt], st + off);
            ldsm4(a2f[mt], st + QTILE_B + off);
        }
        // B fragments (16 n-rows x 32 int8 per nb): proven brow/bcol mapping
        const uint32_t brow = (uint32_t)(((lane >> 4) << 3) + (lane & 7));
        const uint32_t bcol = (uint32_t)(((lane >> 3) & 1) * 16);
        uint32_t b1f[2][4], b2f[2][4];
#pragma unroll
        for (int nb = 0; nb < 2; nb++) {
            const uint32_t off = (uint32_t)(wn * 32 + nb * 16 + brow) * T48 + bcol;
            ldsm4(b1f[nb], st + 2 * QTILE_B + off);
            ldsm4(b2f[nb], st + 3 * QTILE_B + off);
        }
#pragma unroll
        for (int mt = 0; mt < 4; mt++)
#pragma unroll
            for (int nt = 0; nt < 4; nt++) {
                const uint32_t* b1 = &b1f[nt >> 1][(nt & 1) * 2];
                const uint32_t* b2 = &b2f[nt >> 1][(nt & 1) * 2];
                mma_s8(accH[mt][nt], a1f[mt], b1);   // a1*b1 (weight 16384)
                mma_s8(accM[mt][nt], a1f[mt], b2);   // a1*b2 (weight 128)
                mma_s8(accM[mt][nt], a2f[mt], b1);   // a2*b1 (weight 128)
            }
        __syncthreads();
    }

    // Epilogue: y = sX[m]*sW[n]*(16384*hi + 128*mid) + bias[n]
    const int mrow = lane >> 2, ncol = (lane & 3) * 2;
#pragma unroll
    for (int mt = 0; mt < 4; mt++) {
        const int mA = m0 + wm * 64 + mt * 16 + mrow;
        const float sxa = __ldg(&g_sx[mA]);
        const float sxb = __ldg(&g_sx[mA + 8]);
#pragma unroll
        for (int nt = 0; nt < 4; nt++) {
            const int n = n0 + wn * 32 + nt * 8 + ncol;
            const float sw0 = __ldg(&sW[n]), sw1 = __ldg(&sW[n + 1]);
            const float b0 = __ldg(&bias[n]), b1v = __ldg(&bias[n + 1]);
            float h0 = (float)(int)accH[mt][nt][0], m0v = (float)(int)accM[mt][nt][0];
            float h1 = (float)(int)accH[mt][nt][1], m1v = (float)(int)accM[mt][nt][1];
            float h2 = (float)(int)accH[mt][nt][2], m2v = (float)(int)accM[mt][nt][2];
            float h3 = (float)(int)accH[mt][nt][3], m3v = (float)(int)accM[mt][nt][3];
            float* y0 = Y + (size_t)mA * 1024 + n;
            float* y1 = Y + (size_t)(mA + 8) * 1024 + n;
            *(float2*)y0 = make_float2(sxa * sw0 * (h0 * 16384.f + m0v * 128.f) + b0,
                                       sxa * sw1 * (h1 * 16384.f + m1v * 128.f) + b1v);
            *(float2*)y1 = make_float2(sxb * sw0 * (h2 * 16384.f + m2v * 128.f) + b0,
                                       sxb * sw1 * (h3 * 16384.f + m3v * 128.f) + b1v);
        }
    }
}

// ---------------------------------------------------------------------------
// feat_kv v3 (unchanged): 512 thr, grid 1024, 50% occ.
// ---------------------------------------------------------------------------
#define FK_SMEM 82944
__global__ __launch_bounds__(512, 2) void feat_kv_kernel(const float* __restrict__ Pm)
{
    extern __shared__ float sm[];
    float (*Ps)[68]  = (float(*)[68])sm;
    float (*ks)[64]  = (float(*)[64])(sm + 4352);
    float (*vs)[64]  = (float(*)[64])(sm + 8448);
    float (*kf)[128] = (float(*)[128])(sm + 12544);

    const int tid = threadIdx.x, lane = tid & 31, warp = tid >> 5;
    const int bid = blockIdx.x;
    const int bh = bid >> 4, ch = bid & 15;
    const int b = bh >> 4, h = bh & 15;
    const size_t hb = (size_t)(b * N_) * E_ + h * 64;
    const int row0 = ch * 256;

    for (int i = tid; i < 4096; i += 512) Ps[i >> 6][i & 63] = Pm[i];
    __syncthreads();

    const int eg = tid >> 4, dg = tid & 15;
    float acc[4][4];
#pragma unroll
    for (int i = 0; i < 4; i++)
#pragma unroll
        for (int j = 0; j < 4; j++) acc[i][j] = 0.f;

    for (int t0 = 0; t0 < 256; t0 += 64) {
#pragma unroll
        for (int j = 0; j < 4; j++) {
            const int rl = warp * 4 + j;
            const int row = row0 + t0 + rl;
            const float* kr = g_k + hb + (size_t)row * E_;
            const float* vr = g_v + hb + (size_t)row * E_;
            float2 k2 = ((const float2*)kr)[lane];
            float2 v2 = ((const float2*)vr)[lane];
            ((float2*)vs[rl])[lane] = v2;
            float ss = k2.x * k2.x + k2.y * k2.y;
#pragma unroll
            for (int off = 16; off; off >>= 1) ss += __shfl_xor_sync(0xffffffffu, ss, off);
            float inv = 1.0f / (sqrtf(ss) + EPSN);
            ((float2*)ks[rl])[lane] = make_float2(k2.x * inv, k2.y * inv);
        }
        float p0[4], p1[4];
#pragma unroll
        for (int j = 0; j < 4; j++) { p0[j] = 0.f; p1[j] = 0.f; }
#pragma unroll
        for (int d4 = 0; d4 < 16; d4++) {
            float4 pa = *(const float4*)&Ps[lane][d4 * 4];
            float4 pb = *(const float4*)&Ps[lane + 32][d4 * 4];
#pragma unroll
            for (int j = 0; j < 4; j++) {
                float4 kk = *(const float4*)&ks[warp * 4 + j][d4 * 4];
                p0[j] += kk.x*pa.x + kk.y*pa.y + kk.z*pa.z + kk.w*pa.w;
                p1[j] += kk.x*pb.x + kk.y*pb.y + kk.z*pb.z + kk.w*pb.w;
            }
        }
#pragma unroll
        for (int j = 0; j < 4; j++) {
            const int rl = warp * 4 + j;
            float s0, c0, s1, c1;
            __sincosf(p0[j] * SCALE, &s0, &c0);
            __sincosf(p1[j] * SCALE, &s1, &c1);
            kf[rl][lane]      = s0 * FSCALE;
            kf[rl][lane + 32] = s1 * FSCALE;
            kf[rl][64 + lane] = c0 * FSCALE;
            kf[rl][96 + lane] = c1 * FSCALE;
        }
        __syncthreads();
#pragma unroll 8
        for (int r = 0; r < 64; r++) {
            float4 v4 = *(const float4*)&vs[r][dg * 4];
            float4 f4 = *(const float4*)&kf[r][eg * 4];
            float fa[4] = {f4.x, f4.y, f4.z, f4.w};
#pragma unroll
            for (int i = 0; i < 4; i++) {
                acc[i][0] = fmaf(fa[i], v4.x, acc[i][0]);
                acc[i][1] = fmaf(fa[i], v4.y, acc[i][1]);
                acc[i][2] = fmaf(fa[i], v4.z, acc[i][2]);
                acc[i][3] = fmaf(fa[i], v4.w, acc[i][3]);
            }
        }
        __syncthreads();
    }

    float* outp = g_kvp + (size_t)bid * 8192;
#pragma unroll
    for (int i = 0; i < 4; i++)
        *(float4*)(outp + (eg * 4 + i) * 64 + dg * 4) =
            make_float4(acc[i][0], acc[i][1], acc[i][2], acc[i][3]);
}

// ---------------------------------------------------------------------------
__global__ __launch_bounds__(256) void kv_reduce_kernel()
{
    int bh = blockIdx.x, tid = threadIdx.x;
    const float4* src = (const float4*)(g_kvp + (size_t)bh * 16 * 8192);
    float4* dst = (float4*)(g_kv + (size_t)bh * 8192);
    for (int i = tid; i < 2048; i += 256) {
        float4 s = src[i];
#pragma unroll
        for (int c = 1; c < 16; c++) {
            float4 t = src[c * 2048 + i];
            s.x += t.x; s.y += t.y; s.z += t.z; s.w += t.w;
        }
        dst[i] = s;
    }
}

// ---------------------------------------------------------------------------
// o_feat v4: same as v3 but writes ao as fp32 into g_k (k is dead).
// ---------------------------------------------------------------------------
#define OF_SMEM 100352
__global__ __launch_bounds__(512, 2) void o_feat_kernel(const float* __restrict__ Pm)
{
    extern __shared__ float sm[];
    float (*Ps)[68]   = (float(*)[68])sm;
    float (*kvt)[132] = (float(*)[132])(sm + 4352);
    float (*qs)[64]   = (float(*)[64])(sm + 12800);
    float (*qf)[128]  = (float(*)[128])(sm + 16896);

    const int tid = threadIdx.x, lane = tid & 31, warp = tid >> 5;
    const int bid = blockIdx.x;
    const int bh = bid >> 4, ch = bid & 15;
    const int b = bh >> 4, h = bh & 15;
    const size_t hb = (size_t)(b * N_) * E_ + h * 64;
    const int row0 = ch * 256;

    for (int i = tid; i < 4096; i += 512) Ps[i >> 6][i & 63] = Pm[i];
    {
        const float* kvg = g_kv + (size_t)bh * 8192;
        for (int i = tid; i < 8192; i += 512) kvt[i & 63][i >> 6] = kvg[i];
    }
    __syncthreads();

    for (int t0 = 0; t0 < 256; t0 += 64) {
#pragma unroll
        for (int j = 0; j < 4; j++) {
            const int rl = warp * 4 + j;
            const int row = row0 + t0 + rl;
            const float* qr = g_q + hb + (size_t)row * E_;
            float2 q2 = ((const float2*)qr)[lane];
            float ss = q2.x * q2.x + q2.y * q2.y;
#pragma unroll
            for (int off = 16; off; off >>= 1) ss += __shfl_xor_sync(0xffffffffu, ss, off);
            float inv = 1.0f / (sqrtf(ss) + EPSN);
            ((float2*)qs[rl])[lane] = make_float2(q2.x * inv, q2.y * inv);
        }
        float p0[4], p1[4];
#pragma unroll
        for (int j = 0; j < 4; j++) { p0[j] = 0.f; p1[j] = 0.f; }
#pragma unroll
        for (int d4 = 0; d4 < 16; d4++) {
            float4 pa = *(const float4*)&Ps[lane][d4 * 4];
            float4 pb = *(const float4*)&Ps[lane + 32][d4 * 4];
#pragma unroll
            for (int j = 0; j < 4; j++) {
                float4 kk = *(const float4*)&qs[warp * 4 + j][d4 * 4];
                p0[j] += kk.x*pa.x + kk.y*pa.y + kk.z*pa.z + kk.w*pa.w;
                p1[j] += kk.x*pb.x + kk.y*pb.y + kk.z*pb.z + kk.w*pb.w;
            }
        }
#pragma unroll
        for (int j = 0; j < 4; j++) {
            const int rl = warp * 4 + j;
            float s0, c0, s1, c1;
            __sincosf(p0[j] * SCALE, &s0, &c0);
            __sincosf(p1[j] * SCALE, &s1, &c1);
            qf[rl][lane]      = s0 * FSCALE;
            qf[rl][lane + 32] = s1 * FSCALE;
            qf[rl][64 + lane] = c0 * FSCALE;
            qf[rl][96 + lane] = c1 * FSCALE;
        }
        __syncthreads();
        float o0[4], o1[4];
#pragma unroll
        for (int j = 0; j < 4; j++) { o0[j] = 0.f; o1[j] = 0.f; }
#pragma unroll
        for (int e4 = 0; e4 < 32; e4++) {
            float4 kv0 = *(const float4*)&kvt[lane][e4 * 4];
            float4 kv1 = *(const float4*)&kvt[lane + 32][e4 * 4];
#pragma unroll
            for (int j = 0; j < 4; j++) {
                float4 q4 = *(const float4*)&qf[warp * 4 + j][e4 * 4];
                o0[j] += q4.x*kv0.x + q4.y*kv0.y + q4.z*kv0.z + q4.w*kv0.w;
                o1[j] += q4.x*kv1.x + q4.y*kv1.y + q4.z*kv1.z + q4.w*kv1.w;
            }
        }
#pragma unroll
        for (int j = 0; j < 4; j++) {
            const int row = row0 + t0 + warp * 4 + j;
            const size_t idx = hb + (size_t)row * E_ + lane;
            g_k[idx]      = o0[j];
            g_k[idx + 32] = o1[j];
        }
        __syncthreads();
    }
}

// ---------------------------------------------------------------------------
extern "C" void kernel_launch(void* const* d_in, const int* in_sizes, int n_in,
                              void* d_out, int out_size)
{
    const float* x  = (const float*)d_in[0];
    const float* Wq = (const float*)d_in[1];
    const float* bq = (const float*)d_in[2];
    const float* Wk = (const float*)d_in[3];
    const float* bk = (const float*)d_in[4];
    const float* Wv = (const float*)d_in[5];
    const float* bv = (const float*)d_in[6];
    const float* Wo = (const float*)d_in[7];
    const float* bo = (const float*)d_in[8];
    const float* P  = (const float*)d_in[9];
    float* out = (float*)d_out;

    cudaFuncSetAttribute(gemm_s8,
                         cudaFuncAttributeMaxDynamicSharedMemorySize, 2 * QSTAGE_B);
    cudaFuncSetAttribute(feat_kv_kernel,
                         cudaFuncAttributeMaxDynamicSharedMemorySize, FK_SMEM);
    cudaFuncSetAttribute(o_feat_kernel,
                         cudaFuncAttributeMaxDynamicSharedMemorySize, OF_SMEM);

    // quantize x and the 4 weight matrices
    quant_rows<<<16384, 256>>>(x,  0, 0);
    quant_rows<<<1024,  256>>>(Wq, 0, 1);
    quant_rows<<<1024,  256>>>(Wk, 0, 2);
    quant_rows<<<1024,  256>>>(Wv, 0, 3);
    quant_rows<<<1024,  256>>>(Wo, 0, 4);

    // fused q/k/v projections (int8 split GEMM)
    gemm_s8<<<dim3(8, 128, 3), 256, 2 * QSTAGE_B>>>(0, bq, bk, bv, nullptr, 0);

    feat_kv_kernel<<<1024, 512, FK_SMEM>>>(P);
    kv_reduce_kernel<<<64, 256>>>();
    o_feat_kernel<<<1024, 512, OF_SMEM>>>(P);     // ao fp32 -> g_k

    // quantize ao (reads g_k, overwrites g_xq/g_sx)
    quant_rows<<<16384, 256>>>(nullptr, 1, 0);

    // output projection
    gemm_s8<<<dim3(8, 128, 1), 256, 2 * QSTAGE_B>>>(3, bo, bo, bo, out, -1);
}

// round 13
// speedup vs baseline: 2.1666x; 2.1666x over previous
#include <cuda_runtime.h>
#include <cuda_bf16.h>
#include <math.h>
#include <cstdint>

// Problem constants
#define B_    4
#define N_    4096
#define E_    1024
#define H_    16
#define MTOT  16384        // B*N
#define EPSN  1e-4f
#define SCALE 2.0f         // H^0.25
#define FSCALE 0.125f      // PD^-0.5

// ---------------------------------------------------------------------------
// Scratch (device globals: allocation-free rule)
// ---------------------------------------------------------------------------
__device__ float g_q [16777216];     // (B,N,E) q proj fp32
__device__ float g_k [16777216];     // (B,N,E) k proj fp32
__device__ float g_v [16777216];     // (B,N,E) v proj fp32
__device__ float g_kvp[8388608];     // per block partial kv (128x64), 1024 blocks
__device__ float g_kv [524288];      // per bh kv (128x64)
__device__ __nv_bfloat16 g_xhi [16777216];
__device__ __nv_bfloat16 g_xlo [16777216];
__device__ __nv_bfloat16 g_aohi[16777216];
__device__ __nv_bfloat16 g_aolo[16777216];
__device__ __nv_bfloat16 g_whi [4194304];   // 4 x 1024x1024
__device__ __nv_bfloat16 g_wlo [4194304];

__device__ __forceinline__ float* sel_buf(int s) {
    return s == 0 ? g_q : (s == 1 ? g_k : g_v);
}

// ---------------------------------------------------------------------------
// PTX helpers (base-target sm_103 safe: mma.sync / ldmatrix / cp.async only)
// ---------------------------------------------------------------------------
__device__ __forceinline__ uint32_t smem_u32(const void* p) {
    uint32_t a;
    asm("{ .reg .u64 t; cvta.to.shared.u64 t, %1; cvt.u32.u64 %0, t; }"
        : "=r"(a) : "l"(p));
    return a;
}
__device__ __forceinline__ void cpasync16(uint32_t dst, const void* src) {
    asm volatile("cp.async.cg.shared.global [%0], [%1], 16;" :: "r"(dst), "l"(src));
}
#define CP_COMMIT()  asm volatile("cp.async.commit_group;" ::: "memory")
#define CP_WAIT(n)   asm volatile("cp.async.wait_group %0;" :: "n"(n) : "memory")

__device__ __forceinline__ void ldsm4(uint32_t* r, uint32_t addr) {
    asm volatile("ldmatrix.sync.aligned.m8n8.x4.shared.b16 {%0,%1,%2,%3}, [%4];"
                 : "=r"(r[0]), "=r"(r[1]), "=r"(r[2]), "=r"(r[3]) : "r"(addr));
}
__device__ __forceinline__ void mma16816(float* d, const uint32_t* a, const uint32_t* b) {
    asm volatile(
        "mma.sync.aligned.m16n8k16.row.col.f32.bf16.bf16.f32 "
        "{%0,%1,%2,%3}, {%4,%5,%6,%7}, {%8,%9}, {%0,%1,%2,%3};"
        : "+f"(d[0]), "+f"(d[1]), "+f"(d[2]), "+f"(d[3])
        : "r"(a[0]), "r"(a[1]), "r"(a[2]), "r"(a[3]), "r"(b[0]), "r"(b[1]));
}

// ---------------------------------------------------------------------------
// Split conversions: fp32 -> bf16 hi + bf16 lo.
// ---------------------------------------------------------------------------
__device__ __forceinline__ void split_store(const float4 v, __nv_bfloat16* hi,
                                            __nv_bfloat16* lo, int i)
{
    __nv_bfloat16 h0 = __float2bfloat16(v.x);
    __nv_bfloat16 h1 = __float2bfloat16(v.y);
    __nv_bfloat16 h2 = __float2bfloat16(v.z);
    __nv_bfloat16 h3 = __float2bfloat16(v.w);
    __nv_bfloat162* hp = (__nv_bfloat162*)hi;
    __nv_bfloat162* lp = (__nv_bfloat162*)lo;
    hp[i * 2]     = __nv_bfloat162(h0, h1);
    hp[i * 2 + 1] = __nv_bfloat162(h2, h3);
    lp[i * 2]     = __nv_bfloat162(__float2bfloat16(v.x - __bfloat162float(h0)),
                                   __float2bfloat16(v.y - __bfloat162float(h1)));
    lp[i * 2 + 1] = __nv_bfloat162(__float2bfloat16(v.z - __bfloat162float(h2)),
                                   __float2bfloat16(v.w - __bfloat162float(h3)));
}

__global__ __launch_bounds__(256) void conv_x(const float* __restrict__ src)
{
    int i = blockIdx.x * 256 + threadIdx.x;
    split_store(((const float4*)src)[i], g_xhi, g_xlo, i);
}

__global__ __launch_bounds__(256) void conv_w(
    const float* __restrict__ w0, const float* __restrict__ w1,
    const float* __restrict__ w2, const float* __restrict__ w3)
{
    int z = blockIdx.y;
    const float* src = z == 0 ? w0 : (z == 1 ? w1 : (z == 2 ? w2 : w3));
    int i = blockIdx.x * 256 + threadIdx.x;
    split_store(((const float4*)src)[i],
                g_whi + (size_t)z * 1048576, g_wlo + (size_t)z * 1048576, i);
}

// ---------------------------------------------------------------------------
// Tensor-core GEMM (NT) via mma.sync bf16 split:
// Y[16384,1024] = X @ W^T + bias.  grid (4, 128, nz); z selects W/bias/dst.
// 128x256 block, K-chunk 32, 256 thr (2x4 warps, 64x64 warp tile),
// 3-stage cp.async pipeline (60KB/stage, 180KB total), 1 sync/chunk.
// ---------------------------------------------------------------------------
#define A_TILE_B 10240     // 128 rows * 80 bytes
#define B_TILE_B 20480     // 256 rows * 80 bytes
#define STAGE_B  61440     // Ahi|Alo|Bhi|Blo
#define NSTAGE   3
__global__ __launch_bounds__(256, 1) void gemm_mma(
    int xsel, int wsel_base,
    const float* __restrict__ bias0, const float* __restrict__ bias1,
    const float* __restrict__ bias2,
    float* __restrict__ Yext, int ysel_base)
{
    const int z = blockIdx.z;
    const int wsel = wsel_base + z;
    const float* bias = z == 0 ? bias0 : (z == 1 ? bias1 : bias2);
    const __nv_bfloat16* Xhi = xsel ? g_aohi : g_xhi;
    const __nv_bfloat16* Xlo = xsel ? g_aolo : g_xlo;
    const __nv_bfloat16* Whi = g_whi + (size_t)wsel * 1048576;
    const __nv_bfloat16* Wlo = g_wlo + (size_t)wsel * 1048576;
    float* Y = (ysel_base < 0) ? Yext : sel_buf(ysel_base + z);

    extern __shared__ char smem[];
    const uint32_t sbase = smem_u32(smem);
    const int tid = threadIdx.x;
    const int lane = tid & 31, wid = tid >> 5;
    const int wm = wid & 1, wn = wid >> 1;      // warp tile 64 x 64
    const int m0 = blockIdx.y * 128, n0 = blockIdx.x * 256;

    float acc[4][8][4];
#pragma unroll
    for (int a = 0; a < 4; a++)
#pragma unroll
        for (int b = 0; b < 8; b++)
#pragma unroll
            for (int c = 0; c < 4; c++) acc[a][b][c] = 0.f;

    // chunk loader: 3072 x 16B segments, 12 per thread (always commits)
    auto issue_chunk = [&](int c) {
        if (c < 32) {
            const int k0 = c * 32;
            const uint32_t dstb = sbase + (uint32_t)(c % NSTAGE) * STAGE_B;
#pragma unroll
            for (int it = 0; it < 12; it++) {
                const int id = it * 256 + tid;
                const __nv_bfloat16* src;
                uint32_t dst;
                if (id < 1024) {              // A tiles (hi, lo)
                    const int t = id >> 9;
                    const int r = (id & 511) >> 2, seg = id & 3;
                    src = (t ? Xlo : Xhi) + (size_t)(m0 + r) * 1024 + k0 + seg * 8;
                    dst = dstb + t * A_TILE_B + r * 80 + seg * 16;
                } else {                      // B tiles (hi, lo)
                    const int id2 = id - 1024;
                    const int t = id2 >> 10;
                    const int r = (id2 & 1023) >> 2, seg = id2 & 3;
                    src = (t ? Wlo : Whi) + (size_t)(n0 + r) * 1024 + k0 + seg * 8;
                    dst = dstb + 2 * A_TILE_B + t * B_TILE_B + r * 80 + seg * 16;
                }
                cpasync16(dst, src);
            }
        }
        CP_COMMIT();
    };

    issue_chunk(0);
    issue_chunk(1);
    for (int c = 0; c < 32; c++) {
        CP_WAIT(1);            // chunk c landed (groups retire in order)
        __syncthreads();       // all threads past reads of buf (c-1)%3
        issue_chunk(c + 2);    // writes (c+2)%3 == (c-1)%3; overlaps compute
        const uint32_t st = sbase + (uint32_t)(c % NSTAGE) * STAGE_B;
#pragma unroll
        for (int ks = 0; ks < 2; ks++) {
            const uint32_t arow = (uint32_t)(lane & 15);
            const uint32_t acol = (uint32_t)(ks * 16 + (lane >> 4) * 8) * 2;
            uint32_t ahi[4][4], alo[4][4];
#pragma unroll
            for (int mt = 0; mt < 4; mt++) {
                const uint32_t off = (uint32_t)(wm * 64 + mt * 16 + arow) * 80 + acol;
                ldsm4(ahi[mt], st + off);
                ldsm4(alo[mt], st + A_TILE_B + off);
            }
            const uint32_t brow = (uint32_t)(((lane >> 4) << 3) + (lane & 7));
            const uint32_t bcol = (uint32_t)(ks * 16 + ((lane >> 3) & 1) * 8) * 2;
            uint32_t bhi[4][4], blo[4][4];
#pragma unroll
            for (int nb = 0; nb < 4; nb++) {
                const uint32_t off = (uint32_t)(wn * 64 + nb * 16 + brow) * 80 + bcol;
                ldsm4(bhi[nb], st + 2 * A_TILE_B + off);
                ldsm4(blo[nb], st + 2 * A_TILE_B + B_TILE_B + off);
            }
#pragma unroll
            for (int mt = 0; mt < 4; mt++)
#pragma unroll
                for (int nt = 0; nt < 8; nt++) {
                    const uint32_t* bh = &bhi[nt >> 1][(nt & 1) * 2];
                    const uint32_t* bl = &blo[nt >> 1][(nt & 1) * 2];
                    mma16816(acc[mt][nt], ahi[mt], bh);
                    mma16816(acc[mt][nt], ahi[mt], bl);
                    mma16816(acc[mt][nt], alo[mt], bh);
                }
        }
    }

    const int mrow = lane >> 2, ncol = (lane & 3) * 2;
#pragma unroll
    for (int mt = 0; mt < 4; mt++)
#pragma unroll
        for (int nt = 0; nt < 8; nt++) {
            const int m = m0 + wm * 64 + mt * 16 + mrow;
            const int n = n0 + wn * 64 + nt * 8 + ncol;
            const float b0 = __ldg(&bias[n]), b1 = __ldg(&bias[n + 1]);
            float* y0 = Y + (size_t)m * 1024 + n;
            float* y1 = Y + (size_t)(m + 8) * 1024 + n;
            *(float2*)y0 = make_float2(acc[mt][nt][0] + b0, acc[mt][nt][1] + b1);
            *(float2*)y1 = make_float2(acc[mt][nt][2] + b0, acc[mt][nt][3] + b1);
        }
}

// ---------------------------------------------------------------------------
// feat_kv v3: 512 threads (16 warps), grid 1024 = 64 bh x 16 chunks (256 rows),
// tiles of 64 rows.  Thread owns 4e x 4d -> 2 CTAs/SM, 50% occupancy.
// ---------------------------------------------------------------------------
#define FK_SMEM 82944
__global__ __launch_bounds__(512, 2) void feat_kv_kernel(const float* __restrict__ Pm)
{
    extern __shared__ float sm[];
    float (*Ps)[68]  = (float(*)[68])sm;
    float (*ks)[64]  = (float(*)[64])(sm + 4352);
    float (*vs)[64]  = (float(*)[64])(sm + 8448);
    float (*kf)[128] = (float(*)[128])(sm + 12544);

    const int tid = threadIdx.x, lane = tid & 31, warp = tid >> 5;
    const int bid = blockIdx.x;
    const int bh = bid >> 4, ch = bid & 15;
    const int b = bh >> 4, h = bh & 15;
    const size_t hb = (size_t)(b * N_) * E_ + h * 64;
    const int row0 = ch * 256;

    for (int i = tid; i < 4096; i += 512) Ps[i >> 6][i & 63] = Pm[i];
    __syncthreads();

    const int eg = tid >> 4, dg = tid & 15;
    float acc[4][4];
#pragma unroll
    for (int i = 0; i < 4; i++)
#pragma unroll
        for (int j = 0; j < 4; j++) acc[i][j] = 0.f;

    for (int t0 = 0; t0 < 256; t0 += 64) {
#pragma unroll
        for (int j = 0; j < 4; j++) {
            const int rl = warp * 4 + j;
            const int row = row0 + t0 + rl;
            const float* kr = g_k + hb + (size_t)row * E_;
            const float* vr = g_v + hb + (size_t)row * E_;
            float2 k2 = ((const float2*)kr)[lane];
            float2 v2 = ((const float2*)vr)[lane];
            ((float2*)vs[rl])[lane] = v2;
            float ss = k2.x * k2.x + k2.y * k2.y;
#pragma unroll
            for (int off = 16; off; off >>= 1) ss += __shfl_xor_sync(0xffffffffu, ss, off);
            float inv = 1.0f / (sqrtf(ss) + EPSN);
            ((float2*)ks[rl])[lane] = make_float2(k2.x * inv, k2.y * inv);
        }
        float p0[4], p1[4];
#pragma unroll
        for (int j = 0; j < 4; j++) { p0[j] = 0.f; p1[j] = 0.f; }
#pragma unroll
        for (int d4 = 0; d4 < 16; d4++) {
            float4 pa = *(const float4*)&Ps[lane][d4 * 4];
            float4 pb = *(const float4*)&Ps[lane + 32][d4 * 4];
#pragma unroll
            for (int j = 0; j < 4; j++) {
                float4 kk = *(const float4*)&ks[warp * 4 + j][d4 * 4];
                p0[j] += kk.x*pa.x + kk.y*pa.y + kk.z*pa.z + kk.w*pa.w;
                p1[j] += kk.x*pb.x + kk.y*pb.y + kk.z*pb.z + kk.w*pb.w;
            }
        }
#pragma unroll
        for (int j = 0; j < 4; j++) {
            const int rl = warp * 4 + j;
            float s0, c0, s1, c1;
            __sincosf(p0[j] * SCALE, &s0, &c0);
            __sincosf(p1[j] * SCALE, &s1, &c1);
            kf[rl][lane]      = s0 * FSCALE;
            kf[rl][lane + 32] = s1 * FSCALE;
            kf[rl][64 + lane] = c0 * FSCALE;
            kf[rl][96 + lane] = c1 * FSCALE;
        }
        __syncthreads();
#pragma unroll 8
        for (int r = 0; r < 64; r++) {
            float4 v4 = *(const float4*)&vs[r][dg * 4];
            float4 f4 = *(const float4*)&kf[r][eg * 4];
            float fa[4] = {f4.x, f4.y, f4.z, f4.w};
#pragma unroll
            for (int i = 0; i < 4; i++) {
                acc[i][0] = fmaf(fa[i], v4.x, acc[i][0]);
                acc[i][1] = fmaf(fa[i], v4.y, acc[i][1]);
                acc[i][2] = fmaf(fa[i], v4.z, acc[i][2]);
                acc[i][3] = fmaf(fa[i], v4.w, acc[i][3]);
            }
        }
        __syncthreads();
    }

    float* outp = g_kvp + (size_t)bid * 8192;
#pragma unroll
    for (int i = 0; i < 4; i++)
        *(float4*)(outp + (eg * 4 + i) * 64 + dg * 4) =
            make_float4(acc[i][0], acc[i][1], acc[i][2], acc[i][3]);
}

// ---------------------------------------------------------------------------
__global__ __launch_bounds__(256) void kv_reduce_kernel()
{
    int bh = blockIdx.x, tid = threadIdx.x;
    const float4* src = (const float4*)(g_kvp + (size_t)bh * 16 * 8192);
    float4* dst = (float4*)(g_kv + (size_t)bh * 8192);
    for (int i = tid; i < 2048; i += 256) {
        float4 s = src[i];
#pragma unroll
        for (int c = 1; c < 16; c++) {
            float4 t = src[c * 2048 + i];
            s.x += t.x; s.y += t.y; s.z += t.z; s.w += t.w;
        }
        dst[i] = s;
    }
}

// ---------------------------------------------------------------------------
// o_feat v3: 512 threads (16 warps), grid 1024; writes ao bf16 hi/lo splits.
// ---------------------------------------------------------------------------
#define OF_SMEM 100352
__global__ __launch_bounds__(512, 2) void o_feat_kernel(const float* __restrict__ Pm)
{
    extern __shared__ float sm[];
    float (*Ps)[68]   = (float(*)[68])sm;
    float (*kvt)[132] = (float(*)[132])(sm + 4352);
    float (*qs)[64]   = (float(*)[64])(sm + 12800);
    float (*qf)[128]  = (float(*)[128])(sm + 16896);

    const int tid = threadIdx.x, lane = tid & 31, warp = tid >> 5;
    const int bid = blockIdx.x;
    const int bh = bid >> 4, ch = bid & 15;
    const int b = bh >> 4, h = bh & 15;
    const size_t hb = (size_t)(b * N_) * E_ + h * 64;
    const int row0 = ch * 256;

    for (int i = tid; i < 4096; i += 512) Ps[i >> 6][i & 63] = Pm[i];
    {
        const float* kvg = g_kv + (size_t)bh * 8192;
        for (int i = tid; i < 8192; i += 512) kvt[i & 63][i >> 6] = kvg[i];
    }
    __syncthreads();

    for (int t0 = 0; t0 < 256; t0 += 64) {
#pragma unroll
        for (int j = 0; j < 4; j++) {
            const int rl = warp * 4 + j;
            const int row = row0 + t0 + rl;
            const float* qr = g_q + hb + (size_t)row * E_;
            float2 q2 = ((const float2*)qr)[lane];
            float ss = q2.x * q2.x + q2.y * q2.y;
#pragma unroll
            for (int off = 16; off; off >>= 1) ss += __shfl_xor_sync(0xffffffffu, ss, off);
            float inv = 1.0f / (sqrtf(ss) + EPSN);
            ((float2*)qs[rl])[lane] = make_float2(q2.x * inv, q2.y * inv);
        }
        float p0[4], p1[4];
#pragma unroll
        for (int j = 0; j < 4; j++) { p0[j] = 0.f; p1[j] = 0.f; }
#pragma unroll
        for (int d4 = 0; d4 < 16; d4++) {
            float4 pa = *(const float4*)&Ps[lane][d4 * 4];
            float4 pb = *(const float4*)&Ps[lane + 32][d4 * 4];
#pragma unroll
            for (int j = 0; j < 4; j++) {
                float4 kk = *(const float4*)&qs[warp * 4 + j][d4 * 4];
                p0[j] += kk.x*pa.x + kk.y*pa.y + kk.z*pa.z + kk.w*pa.w;
                p1[j] += kk.x*pb.x + kk.y*pb.y + kk.z*pb.z + kk.w*pb.w;
            }
        }
#pragma unroll
        for (int j = 0; j < 4; j++) {
            const int rl = warp * 4 + j;
            float s0, c0, s1, c1;
            __sincosf(p0[j] * SCALE, &s0, &c0);
            __sincosf(p1[j] * SCALE, &s1, &c1);
            qf[rl][lane]      = s0 * FSCALE;
            qf[rl][lane + 32] = s1 * FSCALE;
            qf[rl][64 + lane] = c0 * FSCALE;
            qf[rl][96 + lane] = c1 * FSCALE;
        }
        __syncthreads();
        float o0[4], o1[4];
#pragma unroll
        for (int j = 0; j < 4; j++) { o0[j] = 0.f; o1[j] = 0.f; }
#pragma unroll
        for (int e4 = 0; e4 < 32; e4++) {
            float4 kv0 = *(const float4*)&kvt[lane][e4 * 4];
            float4 kv1 = *(const float4*)&kvt[lane + 32][e4 * 4];
#pragma unroll
            for (int j = 0; j < 4; j++) {
                float4 q4 = *(const float4*)&qf[warp * 4 + j][e4 * 4];
                o0[j] += q4.x*kv0.x + q4.y*kv0.y + q4.z*kv0.z + q4.w*kv0.w;
                o1[j] += q4.x*kv1.x + q4.y*kv1.y + q4.z*kv1.z + q4.w*kv1.w;
            }
        }
#pragma unroll
        for (int j = 0; j < 4; j++) {
            const int row = row0 + t0 + warp * 4 + j;
            const size_t idx = hb + (size_t)row * E_ + lane;
            __nv_bfloat16 h0 = __float2bfloat16(o0[j]);
            __nv_bfloat16 h1 = __float2bfloat16(o1[j]);
            g_aohi[idx]      = h0;
            g_aohi[idx + 32] = h1;
            g_aolo[idx]      = __float2bfloat16(o0[j] - __bfloat162float(h0));
            g_aolo[idx + 32] = __float2bfloat16(o1[j] - __bfloat162float(h1));
        }
        __syncthreads();
    }
}

// ---------------------------------------------------------------------------
extern "C" void kernel_launch(void* const* d_in, const int* in_sizes, int n_in,
                              void* d_out, int out_size)
{
    const float* x  = (const float*)d_in[0];
    const float* Wq = (const float*)d_in[1];
    const float* bq = (const float*)d_in[2];
    const float* Wk = (const float*)d_in[3];
    const float* bk = (const float*)d_in[4];
    const float* Wv = (const float*)d_in[5];
    const float* bv = (const float*)d_in[6];
    const float* Wo = (const float*)d_in[7];
    const float* bo = (const float*)d_in[8];
    const float* P  = (const float*)d_in[9];
    float* out = (float*)d_out;

    cudaFuncSetAttribute(gemm_mma,
                         cudaFuncAttributeMaxDynamicSharedMemorySize, NSTAGE * STAGE_B);
    cudaFuncSetAttribute(feat_kv_kernel,
                         cudaFuncAttributeMaxDynamicSharedMemorySize, FK_SMEM);
    cudaFuncSetAttribute(o_feat_kernel,
                         cudaFuncAttributeMaxDynamicSharedMemorySize, OF_SMEM);

    conv_x<<<16384, 256>>>(x);
    conv_w<<<dim3(1024, 4), 256>>>(Wq, Wk, Wv, Wo);

    // fused q/k/v projections
    gemm_mma<<<dim3(4, 128, 3), 256, NSTAGE * STAGE_B>>>(
        0, 0, bq, bk, bv, nullptr, 0);

    feat_kv_kernel<<<1024, 512, FK_SMEM>>>(P);
    kv_reduce_kernel<<<64, 256>>>();
    o_feat_kernel<<<1024, 512, OF_SMEM>>>(P);     // -> g_aohi/g_aolo

    // output projection
    gemm_mma<<<dim3(4, 128, 1), 256, NSTAGE * STAGE_B>>>(
        1, 3, bo, bo, bo, out, -1);
}